// round 13
// baseline (speedup 1.0000x reference)
#include <cuda_runtime.h>
#include <cuda_bf16.h>

// SelfBallPointQuery: B=16, C=3, N=2048, RADIUS=0.2, MAX_SAMPLES=64
// Output float32 (B, N, 64): first 64 ascending in-radius indices, padded
// with the first in-radius index.
//
// R13: phase-split. Phase 1 computes hit BITMASKS only (f32x2 packed by
// QUERY: each lane tests one point against two queries per instruction;
// per-half math identical to the benched-exact scalar form, with -p
// pre-negated in smem so q + (-p) == q - p). Masks go to smem. Phase 2:
// lanes 0..3 walk their query's 64 masks with ffs loops, paying position
// bookkeeping per HIT (~41) instead of per iteration (2048). R12 profile
// showed the ballot/popc/store chain (alu 39%) dominating the halved FP.

#define BQ_B 16
#define BQ_N 2048
#define BQ_MS 64
#define BQ_Q 4                          // queries per warp
#define BQ_WPB 4                        // warps per block
#define BQ_THREADS (BQ_WPB * 32)        // 128
#define BQ_QPB (BQ_WPB * BQ_Q)          // 16 queries per block
#define BQ_BPB (BQ_N / BQ_QPB)          // 128 blocks per batch
#define BQ_G (BQ_N / 32)                // 64 point-groups of 32
#define BQ_R2 0.04f

#define ADD2(d, a, b) asm("add.rn.f32x2 %0, %1, %2;" : "=l"(d) : "l"(a), "l"(b))
#define MUL2(d, a, b) asm("mul.rn.f32x2 %0, %1, %2;" : "=l"(d) : "l"(a), "l"(b))
#define FMA2(d, a, b, c) asm("fma.rn.f32x2 %0, %1, %2, %3;" : "=l"(d) : "l"(a), "l"(b), "l"(c))
#define UNPK(lo, hi, a) asm("mov.b64 {%0, %1}, %2;" : "=f"(lo), "=f"(hi) : "l"(a))
#define PACK2(d, lo, hi) asm("mov.b64 %0, {%1, %2};" : "=l"(d) : "f"(lo), "f"(hi))

__global__ __launch_bounds__(BQ_THREADS, 8)
void SelfBallPointQuery_56736517980692_kernel(const float* __restrict__ pcs,
                                              float* __restrict__ out) {
    __shared__ float sx[BQ_N], sy[BQ_N], sz[BQ_N];      // NEGATED coords, 24 KB
    __shared__ unsigned msk[BQ_WPB][BQ_G][BQ_Q];        // hit masks, 4 KB

    const int b   = blockIdx.x / BQ_BPB;
    const int blk = blockIdx.x % BQ_BPB;
    const float* base = pcs + (size_t)b * 3 * BQ_N;     // [c][n]: x,+N y,+2N z

    for (int n = threadIdx.x; n < BQ_N; n += BQ_THREADS) {
        sx[n] = -base[n];
        sy[n] = -base[BQ_N + n];
        sz[n] = -base[2 * BQ_N + n];
    }
    __syncthreads();

    const int warp = threadIdx.x >> 5;
    const int lane = threadIdx.x & 31;
    const int i0 = blk * BQ_QPB + warp * BQ_Q;          // this warp's 4 queries

    // Query coords packed {q(2i), q(2i+1)} per 64-bit reg.
    unsigned long long qpx[2], qpy[2], qpz[2];
#pragma unroll
    for (int i = 0; i < 2; ++i) {
        PACK2(qpx[i], base[i0 + 2 * i],            base[i0 + 2 * i + 1]);
        PACK2(qpy[i], base[BQ_N + i0 + 2 * i],     base[BQ_N + i0 + 2 * i + 1]);
        PACK2(qpz[i], base[2 * BQ_N + i0 + 2 * i], base[2 * BQ_N + i0 + 2 * i + 1]);
    }
    float* row0 = out + (size_t)(b * BQ_N + i0) * BQ_MS;
    const bool l0 = (lane == 0);

    // ---- Phase 1: hit masks only ----
#pragma unroll 4
    for (int g = 0; g < BQ_G; ++g) {
        const int s = (g << 5) + lane;
        const float px = sx[s], py = sy[s], pz = sz[s];   // negated point
        unsigned long long pxd, pyd, pzd;
        PACK2(pxd, px, px);
        PACK2(pyd, py, py);
        PACK2(pzd, pz, pz);
#pragma unroll
        for (int i = 0; i < 2; ++i) {
            unsigned long long dx, dy, dz, acc;
            ADD2(dx, qpx[i], pxd);              // q + (-p) == q - p, exact
            ADD2(dy, qpy[i], pyd);
            ADD2(dz, qpz[i], pzd);
            MUL2(acc, dx, dx);                  // r(dx*dx)
            FMA2(acc, dy, dy, acc);             // fma(dy,dy,.)
            FMA2(acc, dz, dz, acc);             // fma(dz,dz,.)  == benched-exact form
            float alo, ahi;
            UNPK(alo, ahi, acc);
            const unsigned m0 = __ballot_sync(0xffffffffu, alo < BQ_R2);
            const unsigned m1 = __ballot_sync(0xffffffffu, ahi < BQ_R2);
            if (l0) *(uint2*)&msk[warp][g][2 * i] = make_uint2(m0, m1);
        }
    }
    __syncwarp();   // order mask STS before phase-2 LDS (intra-warp)

    // ---- Phase 2: sparse emit, lanes 0..3 (one per query) ----
    int cnt = 0;
    float firstf = 0.0f;
    if (lane < BQ_Q) {
        float* rowq = row0 + (lane << 6);
        for (int g = 0; g < BQ_G && cnt < BQ_MS; ++g) {
            unsigned m = msk[warp][g][lane];
            const int jb = g << 5;
            while (m) {
                const int bpos = __ffs(m) - 1;
                const float jv = (float)(jb + bpos);   // ascending j order
                if (cnt == 0) firstf = jv;
                rowq[cnt] = jv;
                if (++cnt == BQ_MS) break;
                m &= (m - 1);
            }
        }
    }

    // ---- Padding (lane-parallel), first index broadcast via shfl ----
#pragma unroll
    for (int q = 0; q < BQ_Q; ++q) {
        const int start = __shfl_sync(0xffffffffu, cnt, q);
        const float f   = __shfl_sync(0xffffffffu, firstf, q);
        for (int k = start + lane; k < BQ_MS; k += 32) {
            row0[(q << 6) + k] = f;
        }
    }
}

extern "C" void kernel_launch(void* const* d_in, const int* in_sizes, int n_in,
                              void* d_out, int out_size) {
    (void)in_sizes; (void)n_in; (void)out_size;
    const float* pcs = (const float*)d_in[0];
    float*       out = (float*)d_out;
    dim3 grid(BQ_B * BQ_BPB);   // 2048 blocks
    dim3 block(BQ_THREADS);     // 128 threads
    SelfBallPointQuery_56736517980692_kernel<<<grid, block>>>(pcs, out);
}

// round 14
// speedup vs baseline: 1.1273x; 1.1273x over previous
#include <cuda_runtime.h>
#include <cuda_bf16.h>

// SelfBallPointQuery: B=16, C=3, N=2048, RADIUS=0.2, MAX_SAMPLES=64
// Output float32 (B, N, 64): first 64 ascending in-radius indices, padded
// with the first in-radius index.
//
// R14 = R12 (45.5us champion: f32x2 point-pair math, ballot compaction)
// with register-footprint cuts for occupancy. R12 ran at 64 regs -> 8
// blocks/SM (occ 41%, issue 66%); the instruction stream supports ~30us at
// full issue. Changes: __launch_bounds__(128,9) (56-reg budget; smem allows
// 9 blocks), outer unroll removed (halves live temps), jf_hi derived not
// carried. Math/emission identical to the benched rel_err=0.0 R12.

#define BQ_B 16
#define BQ_N 2048
#define BQ_MS 64
#define BQ_Q 4                          // queries per warp
#define BQ_WPB 4                        // warps per block
#define BQ_THREADS (BQ_WPB * 32)        // 128
#define BQ_QPB (BQ_WPB * BQ_Q)          // 16 queries per block
#define BQ_BPB (BQ_N / BQ_QPB)          // 128 blocks per batch
#define BQ_R2 0.04f
#define BQ_GROUPS (BQ_N / 64)           // 32 groups of 64 points
#define BQ_SLOTS (BQ_GROUPS * 32)       // 1024 pair-slots per coord

#define ADD2(d, a, b) asm("add.rn.f32x2 %0, %1, %2;" : "=l"(d) : "l"(a), "l"(b))
#define MUL2(d, a, b) asm("mul.rn.f32x2 %0, %1, %2;" : "=l"(d) : "l"(a), "l"(b))
#define FMA2(d, a, b, c) asm("fma.rn.f32x2 %0, %1, %2, %3;" : "=l"(d) : "l"(a), "l"(b), "l"(c))
#define UNPK(lo, hi, a) asm("mov.b64 {%0, %1}, %2;" : "=f"(lo), "=f"(hi) : "l"(a))

__global__ __launch_bounds__(BQ_THREADS, 9)
void SelfBallPointQuery_56736517980692_kernel(const float* __restrict__ pcs,
                                              float* __restrict__ out) {
    // Coord-split pair layout: slot (g*32+l) holds (coord[g*64+l], coord[g*64+32+l]),
    // both NEGATED (so q + (-p) == q - p bit-exactly). 3 x 8 KB = 24 KB.
    __shared__ unsigned long long sx[BQ_SLOTS], sy[BQ_SLOTS], sz[BQ_SLOTS];

    const int b   = blockIdx.x / BQ_BPB;
    const int blk = blockIdx.x % BQ_BPB;
    const float* base = pcs + (size_t)b * 3 * BQ_N;   // [c][n]: x,+N y,+2N z

    {
        float* fx = (float*)sx; float* fy = (float*)sy; float* fz = (float*)sz;
        for (int n = threadIdx.x; n < BQ_N; n += BQ_THREADS) {
            const int g = n >> 6, r = n & 63, half = r >> 5, l = r & 31;
            const int e = ((g << 5) | l) * 2 + half;
            fx[e] = -base[n];
            fy[e] = -base[BQ_N + n];
            fz[e] = -base[2 * BQ_N + n];
        }
    }
    __syncthreads();

    const int warp = threadIdx.x >> 5;
    const int lane = threadIdx.x & 31;
    const unsigned below = (1u << lane) - 1u;
    const int i0 = blk * BQ_QPB + warp * BQ_Q;        // this warp's 4 queries

    unsigned long long qxp[BQ_Q], qyp[BQ_Q], qzp[BQ_Q];
    int cnt[BQ_Q];
#pragma unroll
    for (int q = 0; q < BQ_Q; ++q) {
        const float x = base[i0 + q];
        const float y = base[BQ_N + i0 + q];
        const float z = base[2 * BQ_N + i0 + q];
        asm("mov.b64 %0, {%1, %1};" : "=l"(qxp[q]) : "f"(x));
        asm("mov.b64 %0, {%1, %1};" : "=l"(qyp[q]) : "f"(y));
        asm("mov.b64 %0, {%1, %1};" : "=l"(qzp[q]) : "f"(z));
        cnt[q] = 0;
    }
    float* row0 = out + (size_t)(b * BQ_N + i0) * BQ_MS;

    float jf_lo = (float)lane;          // j for low half of this lane's pair

#pragma unroll 1
    for (int g = 0; g < BQ_GROUPS; ++g) {
        const int s = (g << 5) + lane;
        const unsigned long long px = sx[s];   // LDS.64, conflict-free
        const unsigned long long py = sy[s];
        const unsigned long long pz = sz[s];
        const float jf_hi = jf_lo + 32.0f;     // derived, not carried

#pragma unroll
        for (int q = 0; q < BQ_Q; ++q) {
            unsigned long long dx, dy, dz, acc;
            ADD2(dx, qxp[q], px);              // q + (-p) == q - p, bit-exact
            ADD2(dy, qyp[q], py);
            ADD2(dz, qzp[q], pz);
            MUL2(acc, dx, dx);                 // r(dx*dx)
            FMA2(acc, dy, dy, acc);            // fma(dy,dy,acc)
            FMA2(acc, dz, dz, acc);            // fma(dz,dz,acc)  == benched-exact
            float alo, ahi;
            UNPK(alo, ahi, acc);

            const bool hlo = alo < BQ_R2;
            const bool hhi = ahi < BQ_R2;
            const unsigned mlo = __ballot_sync(0xffffffffu, hlo);
            const unsigned mhi = __ballot_sync(0xffffffffu, hhi);

            const int plo = cnt[q] + __popc(mlo & below);
            if (hlo && plo < BQ_MS) row0[(q << 6) + plo] = jf_lo;
            const int mid = cnt[q] + __popc(mlo);
            const int phi = mid + __popc(mhi & below);
            if (hhi && phi < BQ_MS) row0[(q << 6) + phi] = jf_hi;
            cnt[q] = mid + __popc(mhi);
        }
        jf_lo += 64.0f;
    }

    // Padding: slot 0 always holds the first in-radius index (self always
    // hits; its compacted position is 0). __syncwarp orders that store.
    __syncwarp();
#pragma unroll
    for (int q = 0; q < BQ_Q; ++q) {
        const int start = cnt[q] < BQ_MS ? cnt[q] : BQ_MS;   // warp-uniform
        if (start < BQ_MS) {
            const float f = row0[q << 6];
            for (int k = start + lane; k < BQ_MS; k += 32) {
                row0[(q << 6) + k] = f;
            }
        }
    }
}

extern "C" void kernel_launch(void* const* d_in, const int* in_sizes, int n_in,
                              void* d_out, int out_size) {
    (void)in_sizes; (void)n_in; (void)out_size;
    const float* pcs = (const float*)d_in[0];
    float*       out = (float*)d_out;
    dim3 grid(BQ_B * BQ_BPB);   // 2048 blocks
    dim3 block(BQ_THREADS);     // 128 threads
    SelfBallPointQuery_56736517980692_kernel<<<grid, block>>>(pcs, out);
}

// round 16
// speedup vs baseline: 1.2833x; 1.1383x over previous
#include <cuda_runtime.h>
#include <cuda_bf16.h>

// SelfBallPointQuery: B=16, C=3, N=2048, RADIUS=0.2, MAX_SAMPLES=64
// Output float32 (B, N, 64): first 64 ascending in-radius indices, padded
// with the first in-radius index.
//
// R15: spatial bucketing. Each block sorts its batch's 2048 points into a
// 5x5 (x,y) grid (cell width 1/4.9 > radius -> +-1-cell neighborhood is a
// provably conservative candidate set, robust to fp rounding). Warp-per-query
// scans ~550 candidates (vs 2048) with the benched-exact distance chain and
// marks hits in a per-query 2048-bit smem bitmap (atomicOr; order-independent
// -> deterministic despite nondeterministic scatter order). A warp-parallel
// popc-prefix + ffs walk emits the first 64 indices in ascending order.

#define BQ_B 16
#define BQ_N 2048
#define BQ_MS 64
#define BQ_R2 0.04f
#define BQ_GRID 5
#define BQ_CELLS (BQ_GRID * BQ_GRID)
#define BQ_SCALE 4.9f
#define BQ_QPB 8                         // queries (warps) per block
#define BQ_THREADS (BQ_QPB * 32)         // 256
#define BQ_BPB (BQ_N / BQ_QPB)           // 256 blocks per batch
#define BQ_PPT (BQ_N / BQ_THREADS)       // 8 points per thread in preproc
#define BQ_WORDS (BQ_N / 32)             // 64 bitmap words

__global__ __launch_bounds__(BQ_THREADS, 6)
void SelfBallPointQuery_56736517980692_kernel(const float* __restrict__ pcs,
                                              float* __restrict__ out) {
    __shared__ float4 spts[BQ_N];                    // sorted pts, .w = idx bits (32 KB)
    __shared__ int cellStart[BQ_CELLS + 1];
    __shared__ int cellPtr[BQ_CELLS];
    __shared__ int cellCnt[BQ_CELLS];
    __shared__ unsigned bitmap[BQ_QPB][BQ_WORDS];    // 2 KB

    const int b  = blockIdx.x / BQ_BPB;
    const int qb = (blockIdx.x % BQ_BPB) * BQ_QPB;
    const float* base = pcs + (size_t)b * 3 * BQ_N;  // [c][n]: x,+N y,+2N z
    const int tid = threadIdx.x;

    // ---- Preprocess: bucket 2048 points into 5x5 (x,y) cells ----
    if (tid < BQ_CELLS) cellCnt[tid] = 0;
    __syncthreads();

    int lc[BQ_PPT];                                  // stash cell ids only
#pragma unroll
    for (int r = 0; r < BQ_PPT; ++r) {
        const int n = r * BQ_THREADS + tid;          // coalesced
        const int cx = (int)(base[n] * BQ_SCALE);
        const int cy = (int)(base[BQ_N + n] * BQ_SCALE);
        lc[r] = cx * BQ_GRID + cy;
        atomicAdd(&cellCnt[lc[r]], 1);
    }
    __syncthreads();

    if (tid == 0) {                                  // 25-entry serial prefix
        int acc = 0;
        for (int c = 0; c < BQ_CELLS; ++c) { cellStart[c] = acc; acc += cellCnt[c]; }
        cellStart[BQ_CELLS] = acc;                   // == 2048
    }
    __syncthreads();
    if (tid < BQ_CELLS) cellPtr[tid] = cellStart[tid];
    __syncthreads();

#pragma unroll
    for (int r = 0; r < BQ_PPT; ++r) {
        const int n = r * BQ_THREADS + tid;
        const int slot = atomicAdd(&cellPtr[lc[r]], 1);
        spts[slot] = make_float4(base[n], base[BQ_N + n], base[2 * BQ_N + n],
                                 __int_as_float(n));
    }
    __syncthreads();

    // ---- Query phase: one warp per query ----
    const int warp = tid >> 5;
    const int lane = tid & 31;
    const int i = qb + warp;
    const float qx = base[i], qy = base[BQ_N + i], qz = base[2 * BQ_N + i];

    const int cx = (int)(qx * BQ_SCALE);
    const int cy = (int)(qy * BQ_SCALE);
    const int xlo = max(cx - 1, 0), xhi = min(cx + 1, BQ_GRID - 1);
    const int ylo = max(cy - 1, 0), yhi = min(cy + 1, BQ_GRID - 1);

    bitmap[warp][lane] = 0u;
    bitmap[warp][lane + 32] = 0u;
    __syncwarp();

    for (int sx = xlo; sx <= xhi; ++sx) {            // <=3 contiguous ranges
        const int s = cellStart[sx * BQ_GRID + ylo];
        const int e = cellStart[sx * BQ_GRID + yhi + 1];
        for (int k0 = s; k0 < e; k0 += 32) {         // warp-uniform trip count
            const int k = k0 + lane;
            const bool pred = k < e;
            const float4 p = spts[pred ? k : s];     // s valid: loop entered => s<e
            const float dx = qx - p.x;
            const float dy = qy - p.y;
            const float dz = qz - p.z;
            float acc = __fmul_rn(dx, dx);           // benched-exact chain
            acc = __fmaf_rn(dy, dy, acc);
            acc = __fmaf_rn(dz, dz, acc);
            if (pred && acc < BQ_R2) {
                const int idx = __float_as_int(p.w);
                atomicOr(&bitmap[warp][idx >> 5], 1u << (idx & 31));
            }
        }
    }
    __syncwarp();

    // ---- Ordered emission from bitmap ----
    const unsigned w0 = bitmap[warp][lane];
    const unsigned w1 = bitmap[warp][lane + 32];
    const int c0 = __popc(w0), c1 = __popc(w1);

    int inc0 = c0;                                   // inclusive scan of c0
#pragma unroll
    for (int d = 1; d < 32; d <<= 1) {
        const int v = __shfl_up_sync(0xffffffffu, inc0, d);
        if (lane >= d) inc0 += v;
    }
    const int t0 = __shfl_sync(0xffffffffu, inc0, 31);
    int inc1 = c1;
#pragma unroll
    for (int d = 1; d < 32; d <<= 1) {
        const int v = __shfl_up_sync(0xffffffffu, inc1, d);
        if (lane >= d) inc1 += v;
    }
    const int t1 = __shfl_sync(0xffffffffu, inc1, 31);
    const int total = t0 + t1;

    float* row = out + (size_t)(b * BQ_N + i) * BQ_MS;
    {
        int pos = inc0 - c0;                         // exclusive prefix
        unsigned m = w0;
        const int jb = lane << 5;
        while (m) {
            const int bt = __ffs(m) - 1;
            if (pos < BQ_MS) row[pos] = (float)(jb + bt);
            ++pos;
            m &= m - 1u;
        }
    }
    {
        int pos = t0 + (inc1 - c1);
        unsigned m = w1;
        const int jb = 1024 + (lane << 5);
        while (m) {
            const int bt = __ffs(m) - 1;
            if (pos < BQ_MS) row[pos] = (float)(jb + bt);
            ++pos;
            m &= m - 1u;
        }
    }

    // ---- Padding with the minimum set bit (first in-radius index) ----
    int cand = w0 ? ((lane << 5) + __ffs(w0) - 1)
                  : (w1 ? (1024 + (lane << 5) + __ffs(w1) - 1) : 0x7fffffff);
#pragma unroll
    for (int d = 16; d; d >>= 1)
        cand = min(cand, __shfl_xor_sync(0xffffffffu, cand, d));
    const int start = total < BQ_MS ? total : BQ_MS;
    const float f = (float)cand;                     // total>=1 (self always hits)
    for (int k = start + lane; k < BQ_MS; k += 32) {
        row[k] = f;
    }
}

extern "C" void kernel_launch(void* const* d_in, const int* in_sizes, int n_in,
                              void* d_out, int out_size) {
    (void)in_sizes; (void)n_in; (void)out_size;
    const float* pcs = (const float*)d_in[0];
    float*       out = (float*)d_out;
    dim3 grid(BQ_B * BQ_BPB);     // 4096 blocks
    dim3 block(BQ_THREADS);       // 256 threads (8 warps = 8 queries)
    SelfBallPointQuery_56736517980692_kernel<<<grid, block>>>(pcs, out);
}